// round 12
// baseline (speedup 1.0000x reference)
#include <cuda_runtime.h>
#include <cstdint>
#include <cstddef>

#define S_LEN 2048
#define B_DIM 64
#define I_DIM 512
#define H_DIM 512
#define G_DIM 2048  // 4*H

// ---------------- scratch (static device globals) -------------------------------
__device__ __align__(16) float g_xw[(size_t)S_LEN * B_DIM * G_DIM];   // 1 GB
__device__ __align__(16) float g_h[2][B_DIM * H_DIM];
__device__ __align__(16) unsigned long long g_flags[128 * 16];  // 128B-strided flags

// ---------------- packed f32x2 helpers ------------------------------------------
__device__ __forceinline__ unsigned long long pk2(float lo, float hi) {
    unsigned long long r;
    asm("mov.b64 %0, {%1, %2};" : "=l"(r) : "f"(lo), "f"(hi));
    return r;
}
__device__ __forceinline__ void upk2(unsigned long long v, float& lo, float& hi) {
    asm("mov.b64 {%0, %1}, %2;" : "=f"(lo), "=f"(hi) : "l"(v));
}
__device__ __forceinline__ void ffma2(unsigned long long& d, unsigned long long a, unsigned long long b) {
    asm("fma.rn.f32x2 %0, %1, %2, %0;" : "+l"(d) : "l"(a), "l"(b));
}
__device__ __forceinline__ unsigned long long addf2(unsigned long long a, unsigned long long b) {
    unsigned long long r;
    asm("add.rn.f32x2 %0, %1, %2;" : "=l"(r) : "l"(a), "l"(b));
    return r;
}
// MUFU-based activations (abs err ~1e-6, far inside 1e-3 budget)
__device__ __forceinline__ float sigmoid_f(float x) {
    return __fdividef(1.0f, 1.0f + __expf(-x));
}
__device__ __forceinline__ float tanh_f(float x) {
    float e = __expf(2.0f * x);
    return 1.0f - __fdividef(2.0f, e + 1.0f);
}
// ---------------- release/acquire flag ops --------------------------------------
__device__ __forceinline__ void st_release_gpu(unsigned long long* p, unsigned long long v) {
    asm volatile("st.release.gpu.u64 [%0], %1;" :: "l"(p), "l"(v) : "memory");
}
__device__ __forceinline__ unsigned long long ld_acquire_gpu(const unsigned long long* p) {
    unsigned long long v;
    asm volatile("ld.acquire.gpu.u64 %0, [%1];" : "=l"(v) : "l"(p) : "memory");
    return v;
}
__device__ __forceinline__ void wait_flag_ge(const unsigned long long* f, unsigned long long tgt) {
    int spins = 0;
    while (ld_acquire_gpu(f) < tgt) {
        if (++spins > 32) { __nanosleep(64); spins = 16; }
    }
}

// =====================================================================
// Kernel 1: xW = x @ W + bias (unchanged — at its f32x2 issue floor)
// =====================================================================
__global__ __launch_bounds__(256, 2) void gemm_xw_kernel(
    const float* __restrict__ x, const float* __restrict__ W,
    const float* __restrict__ bias)
{
    __shared__ float As[8][128];
    __shared__ float Bs[8][128];

    const int t  = threadIdx.x;
    const int m0 = blockIdx.y * 128;
    const int n0 = blockIdx.x * 128;
    const int tx = t & 15;
    const int ty = t >> 4;

    const int arow = t >> 1, akc = (t & 1) * 4;
    const int brow = t >> 5, bnc = (t & 31) * 4;

    unsigned long long acc[8][4];
    #pragma unroll
    for (int m = 0; m < 8; m++)
        #pragma unroll
        for (int n = 0; n < 4; n++) acc[m][n] = 0ULL;

    float4 av = *(const float4*)(x + (size_t)(m0 + arow) * I_DIM + akc);
    float4 bv = *(const float4*)(W + (size_t)brow * G_DIM + n0 + bnc);

    for (int kt = 0; kt < 64; kt++) {
        __syncthreads();
        As[akc + 0][arow] = av.x;
        As[akc + 1][arow] = av.y;
        As[akc + 2][arow] = av.z;
        As[akc + 3][arow] = av.w;
        *(float4*)&Bs[brow][bnc] = bv;
        __syncthreads();
        if (kt < 63) {
            av = *(const float4*)(x + (size_t)(m0 + arow) * I_DIM + (kt + 1) * 8 + akc);
            bv = *(const float4*)(W + (size_t)((kt + 1) * 8 + brow) * G_DIM + n0 + bnc);
        }
        #pragma unroll
        for (int kk = 0; kk < 8; kk++) {
            float4 a01 = *(const float4*)&As[kk][ty * 8];
            float4 a23 = *(const float4*)&As[kk][ty * 8 + 4];
            ulonglong2 b01 = *(const ulonglong2*)&Bs[kk][tx * 8];
            ulonglong2 b23 = *(const ulonglong2*)&Bs[kk][tx * 8 + 4];
            float am[8] = {a01.x, a01.y, a01.z, a01.w, a23.x, a23.y, a23.z, a23.w};
            #pragma unroll
            for (int m = 0; m < 8; m++) {
                unsigned long long aa = pk2(am[m], am[m]);
                ffma2(acc[m][0], aa, b01.x);
                ffma2(acc[m][1], aa, b01.y);
                ffma2(acc[m][2], aa, b23.x);
                ffma2(acc[m][3], aa, b23.y);
            }
        }
    }

    float bb[8];
    #pragma unroll
    for (int i = 0; i < 8; i++) bb[i] = bias[n0 + tx * 8 + i];
    #pragma unroll
    for (int m = 0; m < 8; m++) {
        float c[8];
        upk2(acc[m][0], c[0], c[1]);
        upk2(acc[m][1], c[2], c[3]);
        upk2(acc[m][2], c[4], c[5]);
        upk2(acc[m][3], c[6], c[7]);
        #pragma unroll
        for (int i = 0; i < 8; i++) c[i] += bb[i];
        float* op = g_xw + (size_t)(m0 + ty * 8 + m) * G_DIM + n0 + tx * 8;
        __stcs((float4*)op,       make_float4(c[0], c[1], c[2], c[3]));
        __stcs((float4*)(op + 4), make_float4(c[4], c[5], c[6], c[7]));
    }
}

// =====================================================================
// Kernel 2: persistent recurrence. 256 thr/CTA, grid (64,2) = 128 CTAs,
// two 64-CTA barrier domains.
// FMA phase: warp = k-split ks (16 kq each); lane: CGf = lane&3 (gate,
//   8 cols), BGf = lane>>2 (4 batches). 8c x 4b f32x2 accs.
//   Per kq: 8 u-LDS (4 distinct/warp) + 4 h-LDS (8 distinct/warp) = 12 LDS,
//   64 FFMA2. Mainloop LDS = 1536 warp-inst = 6144 cyc (was 8192).
// U layout: kq pitch 160, col c at (c>>2)*20 + (c&3)*4 (8 groups, 0-cf).
// h layout: row b at b*512 + (b>>2)*4 -> BG stride 2052 = 4 mod 32 (0-cf).
// Reduction: red[slot(ci,bi)*257 + t] overlay on h region; 8 ks-partials
//   summed per cell by the eltwise owner (b = t>>3, hc = t&7).
// =====================================================================
#define UQ_PITCH 160
#define HB(b)    ((b) * 512 + ((b) >> 2) * 4)
#define REDPITCH 257                        // ull per slot row
#define RED_BYTES (32 * REDPITCH * 8)       // 65792
#define SMEM_BYTES (128 * UQ_PITCH * 4 + RED_BYTES)   // 81920 + 65792 = 147712

__global__ __launch_bounds__(256, 1) void lstm_rec_kernel(
    const float* __restrict__ U, float* __restrict__ out, size_t out_size)
{
    extern __shared__ float sm[];
    float* U_s = sm;                        // [128][160] skewed
    float* h_s = sm + 128 * UQ_PITCH;       // skewed h rows / red overlay

    const int t   = threadIdx.x;            // 0..255
    const int j   = blockIdx.x;             // 0..63
    const int bq  = blockIdx.y;             // 0..1 (barrier domain)

    // FMA-phase mapping
    const int ks   = t >> 5;                // warp = k-split, kq ks*16..+15
    const int lane = t & 31;
    const int CGf  = lane & 3;              // gate (8 cols)
    const int BGf  = lane >> 2;             // batch group (4 batches)

    // eltwise-phase mapping (fixed -> carries c_reg)
    const int hc = t & 7;
    const int b  = t >> 3;                  // 0..31
    const int col = j * 8 + hc;
    const int gb  = bq * 32 + b;

    unsigned long long* dom_flags = g_flags + (size_t)bq * 64 * 16;
    unsigned long long* red = (unsigned long long*)h_s;   // [32][257] overlay

    // ---- U slice load (same as R11): col c at (k>>2)*160 + (c>>2)*20 + (c&3)*4 + ki
    for (int idx = t; idx < 512 * 32; idx += 256) {
        int k = idx >> 5;
        int c = idx & 31;
        float v = U[(size_t)k * G_DIM + (c >> 3) * H_DIM + j * 8 + (c & 7)];
        U_s[(k >> 2) * UQ_PITCH + (c >> 2) * 20 + (c & 3) * 4 + (k & 3)] = v;
    }

    // ---- zero h_buf[0]
    {
        float* hz = g_h[0] + (size_t)bq * 32 * H_DIM;
        hz[j * 256 + t] = 0.0f;
    }

    unsigned long long base = ld_acquire_gpu(&dom_flags[j * 16]);

    // init barrier (domain-local)
    __syncthreads();
    if (t == 0) st_release_gpu(&dom_flags[j * 16], base + 1);
    if (t < 64) wait_flag_ge(&dom_flags[t * 16], base + 1);
    __syncthreads();

    float c_reg = 0.0f;

    for (int ts = 0; ts < S_LEN; ts++) {
        const int cur = ts & 1, nxt = cur ^ 1;

        // ---- xW prefetch for owned cell's 4 gates
        float xw[4];
        {
            const float* xb = g_xw + ((size_t)ts * B_DIM + gb) * G_DIM + j * 8 + hc;
            #pragma unroll
            for (int q = 0; q < 4; q++) xw[q] = __ldcs(xb + q * H_DIM);
        }

        // ---- wait for previous step's h
        if (ts > 0) {
            unsigned long long tgt = base + 1 + (unsigned long long)ts;
            if (t < 64) wait_flag_ge(&dom_flags[t * 16], tgt);
            __syncthreads();
        }

        // ---- h tile load: 32 rows x 512 floats, skewed rows, coalesced
        {
            const float* hb = g_h[cur] + (size_t)bq * 32 * H_DIM;
            #pragma unroll
            for (int n = 0; n < 16; n++) {
                int idx = n * 256 + t;
                int row = idx >> 7;
                int c4  = idx & 127;
                float4 v = __ldcg((const float4*)(hb + row * H_DIM + c4 * 4));
                *(float4*)&h_s[HB(row) + c4 * 4] = v;
            }
        }
        __syncthreads();

        // ---- FMA: 8 cols (gate CGf) x 4 batches x 16 kq (split ks)
        unsigned long long acc[8][4];
        #pragma unroll
        for (int ci = 0; ci < 8; ci++)
            #pragma unroll
            for (int bi = 0; bi < 4; bi++) acc[ci][bi] = 0ULL;

        const char* up = (const char*)(U_s + ks * 16 * UQ_PITCH + CGf * 40);
        const char* hp = (const char*)(h_s + HB(BGf * 4)) + ks * 256;
        #pragma unroll 4
        for (int kq = 0; kq < 16; kq++) {
            ulonglong2 u0 = *(const ulonglong2*)(up);
            ulonglong2 u1 = *(const ulonglong2*)(up + 16);
            ulonglong2 u2 = *(const ulonglong2*)(up + 32);
            ulonglong2 u3 = *(const ulonglong2*)(up + 48);
            ulonglong2 u4 = *(const ulonglong2*)(up + 80);
            ulonglong2 u5 = *(const ulonglong2*)(up + 96);
            ulonglong2 u6 = *(const ulonglong2*)(up + 112);
            ulonglong2 u7 = *(const ulonglong2*)(up + 128);
            ulonglong2 h0 = *(const ulonglong2*)(hp);
            ulonglong2 h1 = *(const ulonglong2*)(hp + 2048);
            ulonglong2 h2 = *(const ulonglong2*)(hp + 4096);
            ulonglong2 h3 = *(const ulonglong2*)(hp + 6144);
            ffma2(acc[0][0], h0.x, u0.x); ffma2(acc[0][0], h0.y, u0.y);
            ffma2(acc[0][1], h1.x, u0.x); ffma2(acc[0][1], h1.y, u0.y);
            ffma2(acc[0][2], h2.x, u0.x); ffma2(acc[0][2], h2.y, u0.y);
            ffma2(acc[0][3], h3.x, u0.x); ffma2(acc[0][3], h3.y, u0.y);
            ffma2(acc[1][0], h0.x, u1.x); ffma2(acc[1][0], h0.y, u1.y);
            ffma2(acc[1][1], h1.x, u1.x); ffma2(acc[1][1], h1.y, u1.y);
            ffma2(acc[1][2], h2.x, u1.x); ffma2(acc[1][2], h2.y, u1.y);
            ffma2(acc[1][3], h3.x, u1.x); ffma2(acc[1][3], h3.y, u1.y);
            ffma2(acc[2][0], h0.x, u2.x); ffma2(acc[2][0], h0.y, u2.y);
            ffma2(acc[2][1], h1.x, u2.x); ffma2(acc[2][1], h1.y, u2.y);
            ffma2(acc[2][2], h2.x, u2.x); ffma2(acc[2][2], h2.y, u2.y);
            ffma2(acc[2][3], h3.x, u2.x); ffma2(acc[2][3], h3.y, u2.y);
            ffma2(acc[3][0], h0.x, u3.x); ffma2(acc[3][0], h0.y, u3.y);
            ffma2(acc[3][1], h1.x, u3.x); ffma2(acc[3][1], h1.y, u3.y);
            ffma2(acc[3][2], h2.x, u3.x); ffma2(acc[3][2], h2.y, u3.y);
            ffma2(acc[3][3], h3.x, u3.x); ffma2(acc[3][3], h3.y, u3.y);
            ffma2(acc[4][0], h0.x, u4.x); ffma2(acc[4][0], h0.y, u4.y);
            ffma2(acc[4][1], h1.x, u4.x); ffma2(acc[4][1], h1.y, u4.y);
            ffma2(acc[4][2], h2.x, u4.x); ffma2(acc[4][2], h2.y, u4.y);
            ffma2(acc[4][3], h3.x, u4.x); ffma2(acc[4][3], h3.y, u4.y);
            ffma2(acc[5][0], h0.x, u5.x); ffma2(acc[5][0], h0.y, u5.y);
            ffma2(acc[5][1], h1.x, u5.x); ffma2(acc[5][1], h1.y, u5.y);
            ffma2(acc[5][2], h2.x, u5.x); ffma2(acc[5][2], h2.y, u5.y);
            ffma2(acc[5][3], h3.x, u5.x); ffma2(acc[5][3], h3.y, u5.y);
            ffma2(acc[6][0], h0.x, u6.x); ffma2(acc[6][0], h0.y, u6.y);
            ffma2(acc[6][1], h1.x, u6.x); ffma2(acc[6][1], h1.y, u6.y);
            ffma2(acc[6][2], h2.x, u6.x); ffma2(acc[6][2], h2.y, u6.y);
            ffma2(acc[6][3], h3.x, u6.x); ffma2(acc[6][3], h3.y, u6.y);
            ffma2(acc[7][0], h0.x, u7.x); ffma2(acc[7][0], h0.y, u7.y);
            ffma2(acc[7][1], h1.x, u7.x); ffma2(acc[7][1], h1.y, u7.y);
            ffma2(acc[7][2], h2.x, u7.x); ffma2(acc[7][2], h2.y, u7.y);
            ffma2(acc[7][3], h3.x, u7.x); ffma2(acc[7][3], h3.y, u7.y);
            up += UQ_PITCH * 4;
            hp += 16;
        }

        // ---- h_s reads done; write partials to red overlay (contiguous STS.64)
        __syncthreads();
        #pragma unroll
        for (int ci = 0; ci < 8; ci++)
            #pragma unroll
            for (int bi = 0; bi < 4; bi++)
                red[(ci * 4 + bi) * REDPITCH + t] = acc[ci][bi];
        __syncthreads();

        // ---- reduce 8 ks-partials per gate for owned cell (b, hc)
        float s[4];
        {
            const int slotbase = (hc * 4 + (b & 3)) * REDPITCH;
            const int wid0 = (b >> 2) * 4;
            #pragma unroll
            for (int q = 0; q < 4; q++) {
                unsigned long long v = red[slotbase + wid0 + q];
                #pragma unroll
                for (int k8 = 1; k8 < 8; k8++)
                    v = addf2(v, red[slotbase + k8 * 32 + wid0 + q]);
                float l, h_;
                upk2(v, l, h_);
                s[q] = l + h_ + xw[q];
            }
        }

        float iv = sigmoid_f(s[0]);
        float fv = sigmoid_f(s[1]);
        float gv = tanh_f(s[2]);
        float ov = sigmoid_f(s[3]);

        c_reg = fv * c_reg + iv * gv;
        float hval = ov * tanh_f(c_reg);

        // ---- h store (critical), release, then out store (off-path)
        __stcg(&g_h[nxt][gb * H_DIM + col], hval);
        __syncthreads();
        if (ts < S_LEN - 1 && t == 0)
            st_release_gpu(&dom_flags[j * 16], base + 2 + (unsigned long long)ts);

        __stcs(&out[(size_t)ts * (B_DIM * H_DIM) + gb * H_DIM + col], hval);

        if (ts == S_LEN - 1) {
            const size_t SEQ  = (size_t)S_LEN * B_DIM * H_DIM;
            const size_t need = SEQ + 2 * (size_t)B_DIM * H_DIM;
            if (out_size >= need) {
                out[SEQ + gb * H_DIM + col]                         = hval;
                out[SEQ + (size_t)B_DIM * H_DIM + gb * H_DIM + col] = c_reg;
            }
        }
    }
}

// =====================================================================
extern "C" void kernel_launch(void* const* d_in, const int* in_sizes, int n_in,
                              void* d_out, int out_size) {
    const float* x    = (const float*)d_in[0];
    const float* W    = (const float*)d_in[1];
    const float* U    = (const float*)d_in[2];
    const float* bias = (const float*)d_in[3];
    float* out = (float*)d_out;
    (void)in_sizes; (void)n_in;

    cudaFuncSetAttribute(lstm_rec_kernel,
                         cudaFuncAttributeMaxDynamicSharedMemorySize, SMEM_BYTES);

    dim3 ggrid(G_DIM / 128, (S_LEN * B_DIM) / 128);  // (16, 1024)
    gemm_xw_kernel<<<ggrid, 256>>>(x, W, bias);

    dim3 rgrid(64, 2);  // 128 CTAs, 1/SM (smem-limited) -> all co-resident
    lstm_rec_kernel<<<rgrid, 256, SMEM_BYTES>>>(U, out, (size_t)out_size);
}

// round 13
// speedup vs baseline: 1.1977x; 1.1977x over previous
#include <cuda_runtime.h>
#include <cuda_bf16.h>
#include <mma.h>
#include <cstdint>
#include <cstddef>

using namespace nvcuda;

#define S_LEN 2048
#define B_DIM 64
#define I_DIM 512
#define H_DIM 512
#define G_DIM 2048  // 4*H

// ---------------- scratch (static device globals) -------------------------------
__device__ __align__(16) float g_xw[(size_t)S_LEN * B_DIM * G_DIM];   // 1 GB
__device__ __align__(16) float g_h[2][B_DIM * H_DIM];
__device__ __align__(16) unsigned long long g_flags[128 * 16];  // 128B-strided flags

// ---------------- packed f32x2 helpers ------------------------------------------
__device__ __forceinline__ void upk2(unsigned long long v, float& lo, float& hi) {
    asm("mov.b64 {%0, %1}, %2;" : "=f"(lo), "=f"(hi) : "l"(v));
}
__device__ __forceinline__ void ffma2(unsigned long long& d, unsigned long long a, unsigned long long b) {
    asm("fma.rn.f32x2 %0, %1, %2, %0;" : "+l"(d) : "l"(a), "l"(b));
}
__device__ __forceinline__ unsigned long long addf2(unsigned long long a, unsigned long long b) {
    unsigned long long r;
    asm("add.rn.f32x2 %0, %1, %2;" : "=l"(r) : "l"(a), "l"(b));
    return r;
}
// MUFU-based activations (abs err ~1e-6, far inside 1e-3 budget)
__device__ __forceinline__ float sigmoid_f(float x) {
    return __fdividef(1.0f, 1.0f + __expf(-x));
}
__device__ __forceinline__ float tanh_f(float x) {
    float e = __expf(2.0f * x);
    return 1.0f - __fdividef(2.0f, e + 1.0f);
}
// ---------------- release/acquire flag ops --------------------------------------
__device__ __forceinline__ void st_release_gpu(unsigned long long* p, unsigned long long v) {
    asm volatile("st.release.gpu.u64 [%0], %1;" :: "l"(p), "l"(v) : "memory");
}
__device__ __forceinline__ unsigned long long ld_acquire_gpu(const unsigned long long* p) {
    unsigned long long v;
    asm volatile("ld.acquire.gpu.u64 %0, [%1];" : "=l"(v) : "l"(p) : "memory");
    return v;
}
__device__ __forceinline__ void wait_flag_ge(const unsigned long long* f, unsigned long long tgt) {
    int spins = 0;
    while (ld_acquire_gpu(f) < tgt) {
        if (++spins > 32) { __nanosleep(64); spins = 16; }
    }
}

// =====================================================================
// Kernel 1: xW = x @ W + bias via split-bf16 WMMA (tensor cores).
// x = xh + xl (bf16), W = Wh + Wl (bf16):
//   xW ~= xh@Wh + xh@Wl + xl@Wh   (xl@Wl ~ 2^-18, dropped)
// CTA tile 128x128, K-step 16, 8 warps as 4(M) x 2(N), warp tile 32x64.
// Bias folded in by initializing accumulators from a replicated bias tile.
// =====================================================================
#define ALDM    40      // A smem ldm (elems): 16 h + 16 l + 8 pad
#define BLDM    264     // B smem ldm (elems): 128 h + 128 l + 8 pad
#define BIASLDM 136

__global__ __launch_bounds__(256, 2) void gemm_xw_wmma(
    const float* __restrict__ x, const float* __restrict__ W,
    const float* __restrict__ bias)
{
    __shared__ __nv_bfloat16 A_s[128 * ALDM];       // 10240 B
    __shared__ __nv_bfloat16 B_s[16 * BLDM];        //  8448 B
    __shared__ float bias_s[16 * BIASLDM];          //  8704 B

    const int t  = threadIdx.x;
    const int m0 = blockIdx.y * 128;
    const int n0 = blockIdx.x * 128;
    const int wid   = t >> 5;
    const int warpM = wid & 3;      // 0..3 -> m offset warpM*32
    const int warpN = wid >> 2;     // 0..1 -> n offset warpN*64

    // ---- bias replicated tile: 16 identical rows of bias[n0..n0+128)
    {
        int row = t >> 4;           // 0..15
        int c   = (t & 15) * 8;
        #pragma unroll
        for (int i = 0; i < 8; i++)
            bias_s[row * BIASLDM + c + i] = bias[n0 + c + i];
    }
    __syncthreads();

    wmma::fragment<wmma::accumulator, 16, 16, 16, float> acc[2][4];
    #pragma unroll
    for (int i = 0; i < 2; i++)
        #pragma unroll
        for (int j = 0; j < 4; j++)
            wmma::load_matrix_sync(acc[i][j], bias_s + warpN * 64 + j * 16,
                                   BIASLDM, wmma::mem_row_major);

    for (int kt = 0; kt < 32; kt++) {
        __syncthreads();
        // ---- A tile: x[m0..+128][kt*16..+16] -> bf16 hi/lo
        {
            int row = t >> 1;
            int kc  = (t & 1) * 8;
            const float* src = x + (size_t)(m0 + row) * I_DIM + kt * 16 + kc;
            float4 v0 = *(const float4*)src;
            float4 v1 = *(const float4*)(src + 4);
            float vv[8] = {v0.x, v0.y, v0.z, v0.w, v1.x, v1.y, v1.z, v1.w};
            __nv_bfloat16 hb[8], lb[8];
            #pragma unroll
            for (int i = 0; i < 8; i++) {
                __nv_bfloat16 h = __float2bfloat16_rn(vv[i]);
                hb[i] = h;
                lb[i] = __float2bfloat16_rn(vv[i] - __bfloat162float(h));
            }
            *(uint4*)&A_s[row * ALDM + kc]      = *(uint4*)hb;
            *(uint4*)&A_s[row * ALDM + 16 + kc] = *(uint4*)lb;
        }
        // ---- B tile: W[kt*16..+16][n0..+128] -> bf16 hi/lo
        {
            int krow = t >> 4;
            int c    = (t & 15) * 8;
            const float* src = W + (size_t)(kt * 16 + krow) * G_DIM + n0 + c;
            float4 v0 = *(const float4*)src;
            float4 v1 = *(const float4*)(src + 4);
            float vv[8] = {v0.x, v0.y, v0.z, v0.w, v1.x, v1.y, v1.z, v1.w};
            __nv_bfloat16 hb[8], lb[8];
            #pragma unroll
            for (int i = 0; i < 8; i++) {
                __nv_bfloat16 h = __float2bfloat16_rn(vv[i]);
                hb[i] = h;
                lb[i] = __float2bfloat16_rn(vv[i] - __bfloat162float(h));
            }
            *(uint4*)&B_s[krow * BLDM + c]       = *(uint4*)hb;
            *(uint4*)&B_s[krow * BLDM + 128 + c] = *(uint4*)lb;
        }
        __syncthreads();

        wmma::fragment<wmma::matrix_a, 16, 16, 16, __nv_bfloat16, wmma::row_major> a_h[2], a_l[2];
        #pragma unroll
        for (int i = 0; i < 2; i++) {
            wmma::load_matrix_sync(a_h[i], A_s + (warpM * 32 + i * 16) * ALDM,      ALDM);
            wmma::load_matrix_sync(a_l[i], A_s + (warpM * 32 + i * 16) * ALDM + 16, ALDM);
        }
        #pragma unroll
        for (int j = 0; j < 4; j++) {
            wmma::fragment<wmma::matrix_b, 16, 16, 16, __nv_bfloat16, wmma::row_major> b_h, b_l;
            wmma::load_matrix_sync(b_h, B_s + warpN * 64 + j * 16,       BLDM);
            wmma::load_matrix_sync(b_l, B_s + 128 + warpN * 64 + j * 16, BLDM);
            #pragma unroll
            for (int i = 0; i < 2; i++) {
                wmma::mma_sync(acc[i][j], a_h[i], b_h, acc[i][j]);
                wmma::mma_sync(acc[i][j], a_h[i], b_l, acc[i][j]);
                wmma::mma_sync(acc[i][j], a_l[i], b_h, acc[i][j]);
            }
        }
    }

    // ---- epilogue: store fp32 accumulators straight to gmem
    #pragma unroll
    for (int i = 0; i < 2; i++)
        #pragma unroll
        for (int j = 0; j < 4; j++) {
            float* dst = g_xw + (size_t)(m0 + warpM * 32 + i * 16) * G_DIM
                       + n0 + warpN * 64 + j * 16;
            wmma::store_matrix_sync(dst, acc[i][j], G_DIM, wmma::mem_row_major);
        }
}

// =====================================================================
// Kernel 2: persistent recurrence — EXACT R11 version (19.69 ms best).
// =====================================================================
#define UQ_PITCH 160
#define HBASE(b) ((b) * 512 + ((b) >> 2) * 8)
#define H_FLOATS (HBASE(31) + 512)         // 16440
#define REDPITCH 257
#define SMEM_FLOATS (128 * UQ_PITCH + H_FLOATS)
#define SMEM_BYTES  (SMEM_FLOATS * 4)

__global__ __launch_bounds__(256, 1) void lstm_rec_kernel(
    const float* __restrict__ U, float* __restrict__ out, size_t out_size)
{
    extern __shared__ float sm[];
    float* U_s = sm;                       // [128][160] skewed
    float* h_s = sm + 128 * UQ_PITCH;      // skewed rows; reused as red buffer

    const int t   = threadIdx.x;           // 0..255
    const int j   = blockIdx.x;            // 0..63
    const int bq  = blockIdx.y;            // 0..1  (barrier domain)

    const int q4 = t >> 6;                 // k quarter 0..3
    const int cg = t & 7;                  // col group: cols cg*4..+3
    const int bg = (t >> 3) & 7;           // batch group: b bg*4..+3

    const int hc = t & 7;
    const int b  = t >> 3;                 // 0..31
    const int col = j * 8 + hc;
    const int gb  = bq * 32 + b;

    unsigned long long* dom_flags = g_flags + (size_t)bq * 64 * 16;
    unsigned long long* red = (unsigned long long*)h_s;   // [16][257] overlay

    for (int idx = t; idx < 512 * 32; idx += 256) {
        int k = idx >> 5;
        int c = idx & 31;
        float v = U[(size_t)k * G_DIM + (c >> 3) * H_DIM + j * 8 + (c & 7)];
        U_s[(k >> 2) * UQ_PITCH + (c >> 2) * 20 + (c & 3) * 4 + (k & 3)] = v;
    }

    {
        float* hz = g_h[0] + (size_t)bq * 32 * H_DIM;
        hz[j * 256 + t] = 0.0f;
    }

    unsigned long long base = ld_acquire_gpu(&dom_flags[j * 16]);

    __syncthreads();
    if (t == 0) st_release_gpu(&dom_flags[j * 16], base + 1);
    if (t < 64) wait_flag_ge(&dom_flags[t * 16], base + 1);
    __syncthreads();

    float c_reg = 0.0f;

    for (int ts = 0; ts < S_LEN; ts++) {
        const int cur = ts & 1, nxt = cur ^ 1;

        float xw[4];
        {
            const float* xb = g_xw + ((size_t)ts * B_DIM + gb) * G_DIM + j * 8 + hc;
            #pragma unroll
            for (int q = 0; q < 4; q++) xw[q] = __ldcs(xb + q * H_DIM);
        }

        if (ts > 0) {
            unsigned long long tgt = base + 1 + (unsigned long long)ts;
            if (t < 64) wait_flag_ge(&dom_flags[t * 16], tgt);
            __syncthreads();
        }

        {
            const float* hb = g_h[cur] + (size_t)bq * 32 * H_DIM;
            #pragma unroll
            for (int n = 0; n < 16; n++) {
                int idx = n * 256 + t;
                int row = idx >> 7;
                int c4  = idx & 127;
                float4 v = __ldcg((const float4*)(hb + row * H_DIM + c4 * 4));
                *(float4*)&h_s[HBASE(row) + c4 * 4] = v;
            }
        }
        __syncthreads();

        unsigned long long acc[4][4];
        #pragma unroll
        for (int ci = 0; ci < 4; ci++)
            #pragma unroll
            for (int bi = 0; bi < 4; bi++) acc[ci][bi] = 0ULL;

        const char* up = (const char*)(U_s + q4 * 32 * UQ_PITCH + cg * 20);
        const char* hp = (const char*)(h_s + HBASE(bg * 4)) + q4 * 512;
        #pragma unroll 4
        for (int kq = 0; kq < 32; kq++) {
            ulonglong2 u0 = *(const ulonglong2*)(up);
            ulonglong2 u1 = *(const ulonglong2*)(up + 16);
            ulonglong2 u2 = *(const ulonglong2*)(up + 32);
            ulonglong2 u3 = *(const ulonglong2*)(up + 48);
            ulonglong2 h0 = *(const ulonglong2*)(hp);
            ulonglong2 h1 = *(const ulonglong2*)(hp + 512 * 4);
            ulonglong2 h2 = *(const ulonglong2*)(hp + 1024 * 4);
            ulonglong2 h3 = *(const ulonglong2*)(hp + 1536 * 4);
            ffma2(acc[0][0], h0.x, u0.x); ffma2(acc[0][0], h0.y, u0.y);
            ffma2(acc[0][1], h1.x, u0.x); ffma2(acc[0][1], h1.y, u0.y);
            ffma2(acc[0][2], h2.x, u0.x); ffma2(acc[0][2], h2.y, u0.y);
            ffma2(acc[0][3], h3.x, u0.x); ffma2(acc[0][3], h3.y, u0.y);
            ffma2(acc[1][0], h0.x, u1.x); ffma2(acc[1][0], h0.y, u1.y);
            ffma2(acc[1][1], h1.x, u1.x); ffma2(acc[1][1], h1.y, u1.y);
            ffma2(acc[1][2], h2.x, u1.x); ffma2(acc[1][2], h2.y, u1.y);
            ffma2(acc[1][3], h3.x, u1.x); ffma2(acc[1][3], h3.y, u1.y);
            ffma2(acc[2][0], h0.x, u2.x); ffma2(acc[2][0], h0.y, u2.y);
            ffma2(acc[2][1], h1.x, u2.x); ffma2(acc[2][1], h1.y, u2.y);
            ffma2(acc[2][2], h2.x, u2.x); ffma2(acc[2][2], h2.y, u2.y);
            ffma2(acc[2][3], h3.x, u2.x); ffma2(acc[2][3], h3.y, u2.y);
            ffma2(acc[3][0], h0.x, u3.x); ffma2(acc[3][0], h0.y, u3.y);
            ffma2(acc[3][1], h1.x, u3.x); ffma2(acc[3][1], h1.y, u3.y);
            ffma2(acc[3][2], h2.x, u3.x); ffma2(acc[3][2], h2.y, u3.y);
            ffma2(acc[3][3], h3.x, u3.x); ffma2(acc[3][3], h3.y, u3.y);
            up += UQ_PITCH * 4;
            hp += 16;
        }

        __syncthreads();
        {
            const int w = t;
            #pragma unroll
            for (int ci = 0; ci < 4; ci++)
                #pragma unroll
                for (int bi = 0; bi < 4; bi++)
                    red[(ci * 4 + bi) * REDPITCH + w] = acc[ci][bi];
        }
        __syncthreads();

        float s[4];
        {
            const int slot = (hc & 3) * 4 + (b & 3);
            #pragma unroll
            for (int q = 0; q < 4; q++) {
                int c = q * 8 + hc;
                int tile = (b >> 2) * 8 + (c >> 2);
                unsigned long long v = red[slot * REDPITCH + tile];
                v = addf2(v, red[slot * REDPITCH +  64 + tile]);
                v = addf2(v, red[slot * REDPITCH + 128 + tile]);
                v = addf2(v, red[slot * REDPITCH + 192 + tile]);
                float l, h_;
                upk2(v, l, h_);
                s[q] = l + h_ + xw[q];
            }
        }

        float iv = sigmoid_f(s[0]);
        float fv = sigmoid_f(s[1]);
        float gv = tanh_f(s[2]);
        float ov = sigmoid_f(s[3]);

        c_reg = fv * c_reg + iv * gv;
        float hval = ov * tanh_f(c_reg);

        __stcg(&g_h[nxt][gb * H_DIM + col], hval);
        __syncthreads();
        if (ts < S_LEN - 1 && t == 0)
            st_release_gpu(&dom_flags[j * 16], base + 2 + (unsigned long long)ts);

        __stcs(&out[(size_t)ts * (B_DIM * H_DIM) + gb * H_DIM + col], hval);

        if (ts == S_LEN - 1) {
            const size_t SEQ  = (size_t)S_LEN * B_DIM * H_DIM;
            const size_t need = SEQ + 2 * (size_t)B_DIM * H_DIM;
            if (out_size >= need) {
                out[SEQ + gb * H_DIM + col]                         = hval;
                out[SEQ + (size_t)B_DIM * H_DIM + gb * H_DIM + col] = c_reg;
            }
        }
    }
}

// =====================================================================
extern "C" void kernel_launch(void* const* d_in, const int* in_sizes, int n_in,
                              void* d_out, int out_size) {
    const float* x    = (const float*)d_in[0];
    const float* W    = (const float*)d_in[1];
    const float* U    = (const float*)d_in[2];
    const float* bias = (const float*)d_in[3];
    float* out = (float*)d_out;
    (void)in_sizes; (void)n_in;

    cudaFuncSetAttribute(lstm_rec_kernel,
                         cudaFuncAttributeMaxDynamicSharedMemorySize, SMEM_BYTES);

    dim3 ggrid(G_DIM / 128, (S_LEN * B_DIM) / 128);  // (16, 1024)
    gemm_xw_wmma<<<ggrid, 256>>>(x, W, bias);

    dim3 rgrid(64, 2);  // 128 CTAs, 1/SM (smem-limited) -> all co-resident
    lstm_rec_kernel<<<rgrid, 256, SMEM_BYTES>>>(U, out, (size_t)out_size);
}

// round 15
// speedup vs baseline: 1.6583x; 1.3845x over previous
#include <cuda_runtime.h>
#include <cuda_bf16.h>
#include <mma.h>
#include <cstdint>
#include <cstddef>

using namespace nvcuda;

#define S_LEN 2048
#define B_DIM 64
#define I_DIM 512
#define H_DIM 512
#define G_DIM 2048  // 4*H

// ---------------- scratch (static device globals) -------------------------------
__device__ __align__(16) float g_xw[(size_t)S_LEN * B_DIM * G_DIM];   // 1 GB
__device__ __align__(16) __nv_bfloat16 g_hh[2][B_DIM * H_DIM];        // h hi (bf16)
__device__ __align__(16) __nv_bfloat16 g_hl[2][B_DIM * H_DIM];        // h lo (bf16)
__device__ __align__(16) unsigned long long g_flags[128 * 16];

// ---------------- activations (MUFU; abs err ~1e-6) -----------------------------
__device__ __forceinline__ float sigmoid_f(float x) {
    return __fdividef(1.0f, 1.0f + __expf(-x));
}
__device__ __forceinline__ float tanh_f(float x) {
    float e = __expf(2.0f * x);
    return 1.0f - __fdividef(2.0f, e + 1.0f);
}
// ---------------- release/acquire flag ops --------------------------------------
__device__ __forceinline__ void st_release_gpu(unsigned long long* p, unsigned long long v) {
    asm volatile("st.release.gpu.u64 [%0], %1;" :: "l"(p), "l"(v) : "memory");
}
__device__ __forceinline__ unsigned long long ld_acquire_gpu(const unsigned long long* p) {
    unsigned long long v;
    asm volatile("ld.acquire.gpu.u64 %0, [%1];" : "=l"(v) : "l"(p) : "memory");
    return v;
}
__device__ __forceinline__ void wait_flag_ge(const unsigned long long* f, unsigned long long tgt) {
    int spins = 0;
    while (ld_acquire_gpu(f) < tgt) {
        if (++spins > 32) { __nanosleep(64); spins = 16; }
    }
}

// =====================================================================
// Kernel 1: xW = x @ W + bias via split-bf16 WMMA (unchanged from R13)
// =====================================================================
#define ALDM    40
#define BLDM    264
#define BIASLDM 136

__global__ __launch_bounds__(256, 2) void gemm_xw_wmma(
    const float* __restrict__ x, const float* __restrict__ W,
    const float* __restrict__ bias)
{
    __shared__ __nv_bfloat16 A_s[128 * ALDM];
    __shared__ __nv_bfloat16 B_s[16 * BLDM];
    __shared__ float bias_s[16 * BIASLDM];

    const int t  = threadIdx.x;
    const int m0 = blockIdx.y * 128;
    const int n0 = blockIdx.x * 128;
    const int wid   = t >> 5;
    const int warpM = wid & 3;
    const int warpN = wid >> 2;

    {
        int row = t >> 4;
        int c   = (t & 15) * 8;
        #pragma unroll
        for (int i = 0; i < 8; i++)
            bias_s[row * BIASLDM + c + i] = bias[n0 + c + i];
    }
    __syncthreads();

    wmma::fragment<wmma::accumulator, 16, 16, 16, float> acc[2][4];
    #pragma unroll
    for (int i = 0; i < 2; i++)
        #pragma unroll
        for (int j = 0; j < 4; j++)
            wmma::load_matrix_sync(acc[i][j], bias_s + warpN * 64 + j * 16,
                                   BIASLDM, wmma::mem_row_major);

    for (int kt = 0; kt < 32; kt++) {
        __syncthreads();
        {
            int row = t >> 1;
            int kc  = (t & 1) * 8;
            const float* src = x + (size_t)(m0 + row) * I_DIM + kt * 16 + kc;
            float4 v0 = *(const float4*)src;
            float4 v1 = *(const float4*)(src + 4);
            float vv[8] = {v0.x, v0.y, v0.z, v0.w, v1.x, v1.y, v1.z, v1.w};
            __nv_bfloat16 hb[8], lb[8];
            #pragma unroll
            for (int i = 0; i < 8; i++) {
                __nv_bfloat16 h = __float2bfloat16_rn(vv[i]);
                hb[i] = h;
                lb[i] = __float2bfloat16_rn(vv[i] - __bfloat162float(h));
            }
            *(uint4*)&A_s[row * ALDM + kc]      = *(uint4*)hb;
            *(uint4*)&A_s[row * ALDM + 16 + kc] = *(uint4*)lb;
        }
        {
            int krow = t >> 4;
            int c    = (t & 15) * 8;
            const float* src = W + (size_t)(kt * 16 + krow) * G_DIM + n0 + c;
            float4 v0 = *(const float4*)src;
            float4 v1 = *(const float4*)(src + 4);
            float vv[8] = {v0.x, v0.y, v0.z, v0.w, v1.x, v1.y, v1.z, v1.w};
            __nv_bfloat16 hb[8], lb[8];
            #pragma unroll
            for (int i = 0; i < 8; i++) {
                __nv_bfloat16 h = __float2bfloat16_rn(vv[i]);
                hb[i] = h;
                lb[i] = __float2bfloat16_rn(vv[i] - __bfloat162float(h));
            }
            *(uint4*)&B_s[krow * BLDM + c]       = *(uint4*)hb;
            *(uint4*)&B_s[krow * BLDM + 128 + c] = *(uint4*)lb;
        }
        __syncthreads();

        wmma::fragment<wmma::matrix_a, 16, 16, 16, __nv_bfloat16, wmma::row_major> a_h[2], a_l[2];
        #pragma unroll
        for (int i = 0; i < 2; i++) {
            wmma::load_matrix_sync(a_h[i], A_s + (warpM * 32 + i * 16) * ALDM,      ALDM);
            wmma::load_matrix_sync(a_l[i], A_s + (warpM * 32 + i * 16) * ALDM + 16, ALDM);
        }
        #pragma unroll
        for (int j = 0; j < 4; j++) {
            wmma::fragment<wmma::matrix_b, 16, 16, 16, __nv_bfloat16, wmma::row_major> b_h, b_l;
            wmma::load_matrix_sync(b_h, B_s + warpN * 64 + j * 16,       BLDM);
            wmma::load_matrix_sync(b_l, B_s + 128 + warpN * 64 + j * 16, BLDM);
            #pragma unroll
            for (int i = 0; i < 2; i++) {
                wmma::mma_sync(acc[i][j], a_h[i], b_h, acc[i][j]);
                wmma::mma_sync(acc[i][j], a_h[i], b_l, acc[i][j]);
                wmma::mma_sync(acc[i][j], a_l[i], b_h, acc[i][j]);
            }
        }
    }

    #pragma unroll
    for (int i = 0; i < 2; i++)
        #pragma unroll
        for (int j = 0; j < 4; j++) {
            float* dst = g_xw + (size_t)(m0 + warpM * 32 + i * 16) * G_DIM
                       + n0 + warpN * 64 + j * 16;
            wmma::store_matrix_sync(dst, acc[i][j], G_DIM, wmma::mem_row_major);
        }
}

// =====================================================================
// Kernel 2: persistent recurrence on tensor cores (split-bf16 WMMA).
// 256 thr/CTA, grid (64,2) = 128 CTAs, two 64-CTA barrier domains.
// CTA (j,bq): batches [bq*32,+32), 32 gate cols (c -> (c>>3)*512+j*8+(c&7)).
// U slice (512x32) split hi/lo bf16, PRELOADED as WMMA B-fragments in regs
//   (warp ks owns k [ks*64,+64): 4 ktiles x 2 ntiles x {hi,lo} = 16 frags).
// Per step: h (pre-split bf16 hi/lo in gmem) -> smem -> A-frags;
//   acc = Ah*Uh + Ah*Ul + Al*Uh (fp32); partials -> red smem; 8-way k-reduce
//   by eltwise owner (b=t>>3, hc=t&7); activations; h stored as hi/lo.
// =====================================================================
#define ULD   40            // U_s ldm (bf16), mult of 8
#define ALDA  520           // h A_s ldm (bf16), mult of 8
#define RLD   36            // red pitch (fp32), mult of 4
#define OFF_UH 0
#define OFF_UL (512 * ULD * 2)                    // 40960
#define OFF_AH (OFF_UL + 512 * ULD * 2)           // 81920
#define OFF_AL (OFF_AH + 32 * ALDA * 2)           // 115200
#define OFF_RED (OFF_AL + 32 * ALDA * 2)          // 148480
#define SMEM_REC (OFF_RED + 8 * 32 * RLD * 4)     // 185344

__global__ __launch_bounds__(256, 1) void lstm_rec_kernel(
    const float* __restrict__ U, float* __restrict__ out, size_t out_size)
{
    extern __shared__ char smem[];
    __nv_bfloat16* U_hi = (__nv_bfloat16*)(smem + OFF_UH);   // [512][40]
    __nv_bfloat16* U_lo = (__nv_bfloat16*)(smem + OFF_UL);
    __nv_bfloat16* A_hi = (__nv_bfloat16*)(smem + OFF_AH);   // [32][520]
    __nv_bfloat16* A_lo = (__nv_bfloat16*)(smem + OFF_AL);
    float*         red  = (float*)(smem + OFF_RED);          // 8 x [32][36]

    const int t   = threadIdx.x;           // 0..255
    const int j   = blockIdx.x;            // 0..63
    const int bq  = blockIdx.y;            // 0..1 (barrier domain)
    const int ks  = t >> 5;                // warp id = k-split (64 k each)

    // eltwise ownership (fixed -> carries c_reg)
    const int hc = t & 7;
    const int b  = t >> 3;                 // 0..31
    const int col = j * 8 + hc;
    const int gb  = bq * 32 + b;

    unsigned long long* dom_flags = g_flags + (size_t)bq * 64 * 16;

    // ---- U slice load + split: U_s[k][c] <- U[k][(c>>3)*512 + j*8 + (c&7)]
    for (int idx = t; idx < 512 * 32; idx += 256) {
        int k = idx >> 5;
        int c = idx & 31;
        float v = U[(size_t)k * G_DIM + (c >> 3) * H_DIM + j * 8 + (c & 7)];
        __nv_bfloat16 h = __float2bfloat16_rn(v);
        U_hi[k * ULD + c] = h;
        U_lo[k * ULD + c] = __float2bfloat16_rn(v - __bfloat162float(h));
    }

    // ---- zero h buffers (domain half: 64 CTAs x 256 elems = 32x512)
    {
        size_t o = (size_t)bq * 32 * H_DIM + j * 256 + t;
        g_hh[0][o] = __float2bfloat16_rn(0.0f);
        g_hl[0][o] = __float2bfloat16_rn(0.0f);
    }
    __syncthreads();

    // ---- preload U fragments (persistent in registers)
    wmma::fragment<wmma::matrix_b, 16, 16, 16, __nv_bfloat16, wmma::row_major> Ubh[4][2], Ubl[4][2];
    #pragma unroll
    for (int kt = 0; kt < 4; kt++)
        #pragma unroll
        for (int nt = 0; nt < 2; nt++) {
            int ko = (ks * 64 + kt * 16) * ULD + nt * 16;
            wmma::load_matrix_sync(Ubh[kt][nt], U_hi + ko, ULD);
            wmma::load_matrix_sync(Ubl[kt][nt], U_lo + ko, ULD);
        }

    unsigned long long base = ld_acquire_gpu(&dom_flags[j * 16]);

    // init barrier (domain-local)
    __syncthreads();
    if (t == 0) st_release_gpu(&dom_flags[j * 16], base + 1);
    if (t < 64) wait_flag_ge(&dom_flags[t * 16], base + 1);
    __syncthreads();

    float c_reg = 0.0f;

    for (int ts = 0; ts < S_LEN; ts++) {
        const int cur = ts & 1, nxt = cur ^ 1;

        // ---- xW prefetch for owned cell's 4 gates
        float xw[4];
        {
            const float* xb = g_xw + ((size_t)ts * B_DIM + gb) * G_DIM + j * 8 + hc;
            #pragma unroll
            for (int q = 0; q < 4; q++) xw[q] = __ldcs(xb + q * H_DIM);
        }

        // ---- wait for previous step's h
        if (ts > 0) {
            unsigned long long tgt = base + 1 + (unsigned long long)ts;
            if (t < 64) wait_flag_ge(&dom_flags[t * 16], tgt);
            __syncthreads();
        }

        // ---- h tiles (hi+lo): 32 rows x 512 bf16 each; coalesced uint4
        {
            const __nv_bfloat16* hbh = g_hh[cur] + (size_t)bq * 32 * H_DIM;
            const __nv_bfloat16* hbl = g_hl[cur] + (size_t)bq * 32 * H_DIM;
            #pragma unroll
            for (int n = 0; n < 8; n++) {
                int idx = n * 256 + t;       // 0..2047
                int row = idx >> 6;          // 0..31
                int c8  = idx & 63;          // uint4 index in row
                uint4 vh = __ldcg((const uint4*)(hbh + row * H_DIM + c8 * 8));
                uint4 vl = __ldcg((const uint4*)(hbl + row * H_DIM + c8 * 8));
                *(uint4*)&A_hi[row * ALDA + c8 * 8] = vh;
                *(uint4*)&A_lo[row * ALDA + c8 * 8] = vl;
            }
        }
        __syncthreads();

        // ---- tensor-core mainloop: acc = Ah*Uh + Ah*Ul + Al*Uh
        wmma::fragment<wmma::accumulator, 16, 16, 16, float> acc[2][2];
        #pragma unroll
        for (int mt = 0; mt < 2; mt++)
            #pragma unroll
            for (int nt = 0; nt < 2; nt++)
                wmma::fill_fragment(acc[mt][nt], 0.0f);

        #pragma unroll
        for (int mt = 0; mt < 2; mt++) {
            wmma::fragment<wmma::matrix_a, 16, 16, 16, __nv_bfloat16, wmma::row_major> a_h[4], a_l[4];
            #pragma unroll
            for (int kt = 0; kt < 4; kt++) {
                int ao = mt * 16 * ALDA + ks * 64 + kt * 16;
                wmma::load_matrix_sync(a_h[kt], A_hi + ao, ALDA);
                wmma::load_matrix_sync(a_l[kt], A_lo + ao, ALDA);
            }
            #pragma unroll
            for (int nt = 0; nt < 2; nt++)
                #pragma unroll
                for (int kt = 0; kt < 4; kt++) {
                    wmma::mma_sync(acc[mt][nt], a_h[kt], Ubh[kt][nt], acc[mt][nt]);
                    wmma::mma_sync(acc[mt][nt], a_h[kt], Ubl[kt][nt], acc[mt][nt]);
                    wmma::mma_sync(acc[mt][nt], a_l[kt], Ubh[kt][nt], acc[mt][nt]);
                }
        }

        // ---- partials to smem
        #pragma unroll
        for (int mt = 0; mt < 2; mt++)
            #pragma unroll
            for (int nt = 0; nt < 2; nt++)
                wmma::store_matrix_sync(red + ks * (32 * RLD) + mt * 16 * RLD + nt * 16,
                                        acc[mt][nt], RLD, wmma::mem_row_major);
        __syncthreads();

        // ---- 8-way k-reduction for owned cell (b, hc), 4 gates
        float s[4];
        #pragma unroll
        for (int q = 0; q < 4; q++) {
            int c = q * 8 + hc;
            float v = red[b * RLD + c];
            #pragma unroll
            for (int k8 = 1; k8 < 8; k8++)
                v += red[k8 * (32 * RLD) + b * RLD + c];
            s[q] = v + xw[q];
        }

        float iv = sigmoid_f(s[0]);
        float fv = sigmoid_f(s[1]);
        float gv = tanh_f(s[2]);
        float ov = sigmoid_f(s[3]);

        c_reg = fv * c_reg + iv * gv;
        float hval = ov * tanh_f(c_reg);

        // ---- h split-store (critical), release, then out store (off-path)
        {
            __nv_bfloat16 hh = __float2bfloat16_rn(hval);
            __nv_bfloat16 hl = __float2bfloat16_rn(hval - __bfloat162float(hh));
            g_hh[nxt][gb * H_DIM + col] = hh;
            g_hl[nxt][gb * H_DIM + col] = hl;
        }
        __syncthreads();
        if (ts < S_LEN - 1 && t == 0)
            st_release_gpu(&dom_flags[j * 16], base + 2 + (unsigned long long)ts);

        __stcs(&out[(size_t)ts * (B_DIM * H_DIM) + gb * H_DIM + col], hval);

        if (ts == S_LEN - 1) {
            const size_t SEQ  = (size_t)S_LEN * B_DIM * H_DIM;
            const size_t need = SEQ + 2 * (size_t)B_DIM * H_DIM;
            if (out_size >= need) {
                out[SEQ + gb * H_DIM + col]                         = hval;
                out[SEQ + (size_t)B_DIM * H_DIM + gb * H_DIM + col] = c_reg;
            }
        }
    }
}

// =====================================================================
extern "C" void kernel_launch(void* const* d_in, const int* in_sizes, int n_in,
                              void* d_out, int out_size) {
    const float* x    = (const float*)d_in[0];
    const float* W    = (const float*)d_in[1];
    const float* U    = (const float*)d_in[2];
    const float* bias = (const float*)d_in[3];
    float* out = (float*)d_out;
    (void)in_sizes; (void)n_in;

    cudaFuncSetAttribute(lstm_rec_kernel,
                         cudaFuncAttributeMaxDynamicSharedMemorySize, SMEM_REC);

    dim3 ggrid(G_DIM / 128, (S_LEN * B_DIM) / 128);  // (16, 1024)
    gemm_xw_wmma<<<ggrid, 256>>>(x, W, bias);

    dim3 rgrid(64, 2);  // 128 CTAs, 1/SM (smem-limited) -> all co-resident
    lstm_rec_kernel<<<rgrid, 256, SMEM_REC>>>(U, out, (size_t)out_size);
}